// round 7
// baseline (speedup 1.0000x reference)
#include <cuda_runtime.h>
#include <stdint.h>

// Fp8Unpadding: gather un-padded rows out of a 256-row-padded concatenation.
// M_SPLITS = {1000,2300,512,3777,129,2048,900,1500}, HIDDEN=4096 (f32).
// dst row r maps to src row r + DELTA[group(r)]; DELTA constant per group.
//
// Row boundaries (cumulative m):  1000, 3300, 3812, 7589, 7718, 9766, 10666, 12166
// Row deltas:                        0,   24,   28,   28,   91,  218,   218,   342
//
// R7: 256-bit global accesses (sm_10x ld/st.global.v8.f32 via inline PTX).
// One 16KB row per block, TPB=128, 4 x 32B per thread, front-batched loads,
// streaming (.cs) policy. Same byte-MLP as R6, half the LDG/STG instructions,
// 1024B-per-warp transactions.

static constexpr int HIDDEN_V4  = 4096 / 4;   // 1024 float4 per row
static constexpr int TOTAL_ROWS = 12166;
static constexpr int TPB        = 128;
static constexpr int CHUNKS     = 4;          // 4 x 32B per thread = 128B

struct v8 { float4 a, b; };

__device__ __forceinline__ v8 ld256_cs(const float4* p)
{
    v8 r;
    asm volatile(
        "ld.global.cs.v8.f32 {%0,%1,%2,%3,%4,%5,%6,%7}, [%8];"
        : "=f"(r.a.x), "=f"(r.a.y), "=f"(r.a.z), "=f"(r.a.w),
          "=f"(r.b.x), "=f"(r.b.y), "=f"(r.b.z), "=f"(r.b.w)
        : "l"(p));
    return r;
}

__device__ __forceinline__ void st256_cs(float4* p, const v8& r)
{
    asm volatile(
        "st.global.cs.v8.f32 [%0], {%1,%2,%3,%4,%5,%6,%7,%8};"
        :: "l"(p),
           "f"(r.a.x), "f"(r.a.y), "f"(r.a.z), "f"(r.a.w),
           "f"(r.b.x), "f"(r.b.y), "f"(r.b.z), "f"(r.b.w)
        : "memory");
}

__device__ __forceinline__ int row_delta(int row)
{
    return (row < 1000)  ? 0
         : (row < 3300)  ? 24
         : (row < 7589)  ? 28
         : (row < 7718)  ? 91
         : (row < 10666) ? 218
         :                 342;
}

__global__ void __launch_bounds__(TPB)
unpad_gather_kernel(const float4* __restrict__ in, float4* __restrict__ out)
{
    int row = blockIdx.x;                        // one 16KB row per block
    const float4* __restrict__ src = in  + (row + row_delta(row)) * HIDDEN_V4;
    float4*       __restrict__ dst = out + row * HIDDEN_V4;

    // per-thread base: thread t owns 32B-chunk t within each 4KB stripe
    int t2 = threadIdx.x * 2;                    // float4 units (32B = 2 x float4)

    v8 v[CHUNKS];

    #pragma unroll
    for (int j = 0; j < CHUNKS; j++)
        v[j] = ld256_cs(src + j * (TPB * 2) + t2);

    #pragma unroll
    for (int j = 0; j < CHUNKS; j++)
        st256_cs(dst + j * (TPB * 2) + t2, v[j]);
}

extern "C" void kernel_launch(void* const* d_in, const int* in_sizes, int n_in,
                              void* d_out, int out_size)
{
    const float4* in  = (const float4*)d_in[0];   // f32 [12544, 4096]
    float4*       out = (float4*)d_out;           // f32 [12166, 4096]

    unpad_gather_kernel<<<TOTAL_ROWS, TPB>>>(in, out);
}

// round 8
// speedup vs baseline: 1.0253x; 1.0253x over previous
#include <cuda_runtime.h>
#include <stdint.h>

// Fp8Unpadding: gather un-padded rows out of a 256-row-padded concatenation.
// M_SPLITS = {1000,2300,512,3777,129,2048,900,1500}, HIDDEN=4096 (f32).
// dst row r maps to src row r + DELTA[group(r)]; DELTA constant per group.
//
// Row boundaries (cumulative m):  1000, 3300, 3812, 7589, 7718, 9766, 10666, 12166
// Row deltas:                        0,   24,   28,   28,   91,  218,   218,   342
//
// R8: long-burst variant of the R6 winner. One 16KB row per block, TPB=64,
// 16x float4 per thread, ALL 16 loads front-batched before ALL 16 stores
// (per-warp read train of 16 LDG.128, then write train of 16 STG.128) to
// minimize DRAM read/write turnaround. Streaming (.cs) hints, zero tail.

static constexpr int HIDDEN_V4  = 4096 / 4;   // 1024 float4 per row
static constexpr int TOTAL_ROWS = 12166;
static constexpr int TPB        = 64;
static constexpr int UNROLL     = 16;         // 64 * 16 = 1024 v4 = 1 row

__device__ __forceinline__ int row_delta(int row)
{
    return (row < 1000)  ? 0
         : (row < 3300)  ? 24
         : (row < 7589)  ? 28
         : (row < 7718)  ? 91
         : (row < 10666) ? 218
         :                 342;
}

__global__ void __launch_bounds__(TPB)
unpad_gather_kernel(const float4* __restrict__ in, float4* __restrict__ out)
{
    int row = blockIdx.x;                        // one 16KB row per block
    const float4* __restrict__ src = in  + (row + row_delta(row)) * HIDDEN_V4;
    float4*       __restrict__ dst = out + row * HIDDEN_V4;

    float4 v[UNROLL];

    // long front-batched read train (16 independent LDG.128 per thread)
    #pragma unroll
    for (int j = 0; j < UNROLL; j++)
        v[j] = __ldcs(src + j * TPB + threadIdx.x);

    // write train
    #pragma unroll
    for (int j = 0; j < UNROLL; j++)
        __stcs(dst + j * TPB + threadIdx.x, v[j]);
}

extern "C" void kernel_launch(void* const* d_in, const int* in_sizes, int n_in,
                              void* d_out, int out_size)
{
    const float4* in  = (const float4*)d_in[0];   // f32 [12544, 4096]
    float4*       out = (float4*)d_out;           // f32 [12166, 4096]

    unpad_gather_kernel<<<TOTAL_ROWS, TPB>>>(in, out);
}